// round 1
// baseline (speedup 1.0000x reference)
#include <cuda_runtime.h>
#include <math.h>

#define TT 2048     // tokens
#define HH 2048     // hidden
#define FF 1408     // moe intermediate
#define EE 60       // experts
#define TK 4        // top-k
#define SS 5632     // shared intermediate
#define NP (TT*TK)  // 8192 routed pairs

// ---- scratch (device globals: allocation-free rule) ----
__device__ float g_ybuf[(size_t)TT*SS];   // shared-expert gate/act buffer [T,SS]
__device__ float g_hbuf[(size_t)NP*FF];   // moe per-pair hidden [NP,FF]
__device__ float g_pbuf[(size_t)NP*HH];   // moe per-pair down output [NP,HH]
__device__ float g_topw[NP];
__device__ int   g_topidx[NP];
__device__ float g_sig[TT];
__device__ int   g_off[EE+1];
__device__ int   g_tok[NP];               // position -> token
__device__ int   g_pos[NP];               // pair -> position

// ============================ router ============================
__global__ void router_kernel(const float* __restrict__ x,
                              const float* __restrict__ rw,
                              const float* __restrict__ seg)
{
    int t = blockIdx.x;
    int tid = threadIdx.x;              // 64 threads
    __shared__ float xs[HH];
    __shared__ float lg[EE];
    __shared__ float red[64];
    const float* xr = x + (size_t)t*HH;
    for (int i = tid; i < HH; i += 64) xs[i] = xr[i];
    __syncthreads();
    if (tid < EE) {
        float a=0.f,b=0.f,c=0.f,d=0.f;
        for (int k = 0; k < HH; k += 4) {
            a = fmaf(xs[k+0], rw[(size_t)(k+0)*EE + tid], a);
            b = fmaf(xs[k+1], rw[(size_t)(k+1)*EE + tid], b);
            c = fmaf(xs[k+2], rw[(size_t)(k+2)*EE + tid], c);
            d = fmaf(xs[k+3], rw[(size_t)(k+3)*EE + tid], d);
        }
        lg[tid] = (a+b)+(c+d);
    }
    float p = 0.f;
    for (int k = tid; k < HH; k += 64) p = fmaf(xs[k], seg[k], p);
    red[tid] = p;
    __syncthreads();
    if (tid == 0) {
        float m = lg[0];
        for (int e = 1; e < EE; e++) m = fmaxf(m, lg[e]);
        float s = 0.f;
        for (int e = 0; e < EE; e++) { float v = __expf(lg[e]-m); lg[e] = v; s += v; }
        float inv = 1.f/s;
        for (int e = 0; e < EE; e++) lg[e] *= inv;
        for (int j = 0; j < TK; j++) {
            int bi = 0; float bv = lg[0];
            for (int e = 1; e < EE; e++) { if (lg[e] > bv) { bv = lg[e]; bi = e; } }
            g_topidx[t*TK+j] = bi;
            g_topw[t*TK+j]  = bv;
            lg[bi] = -1.f;
        }
        float ss = 0.f;
        for (int i = 0; i < 64; i++) ss += red[i];
        g_sig[t] = 1.f/(1.f + __expf(-ss));
    }
}

// ================= routing tables (deterministic, no atomics in fill) =================
__global__ void build1_kernel()
{
    __shared__ int cnt[EE];
    int tid = threadIdx.x;              // 256
    if (tid < EE) cnt[tid] = 0;
    __syncthreads();
    for (int p = tid; p < NP; p += 256) atomicAdd(&cnt[g_topidx[p]], 1);
    __syncthreads();
    if (tid == 0) {
        int s = 0;
        for (int e = 0; e < EE; e++) { g_off[e] = s; s += cnt[e]; }
        g_off[EE] = s;
    }
}

__global__ void build2_kernel()
{
    __shared__ int sidx[NP];            // 32 KB
    int tid = threadIdx.x;              // 256, grid 32 -> one thread per pair
    for (int i = tid; i < NP; i += 256) sidx[i] = g_topidx[i];
    __syncthreads();
    int p = blockIdx.x*256 + tid;
    int e = sidx[p];
    int r = 0;
    for (int q = 0; q < p; q++) r += (sidx[q] == e);   // deterministic rank
    int pos = g_off[e] + r;
    g_tok[pos] = p >> 2;
    g_pos[p]   = pos;
}

// ============================ dense GEMM (shared expert) ============================
// MODE 0: g_ybuf = Ain @ B                 (gate)
// MODE 1: g_ybuf = silu(g_ybuf) * (Ain@B)  (up + SiluAndMul)
// MODE 2: Cext   = sigmoid_gate[row] * (g_ybuf @ B)   (down + expert gate)
template<int MODE>
__global__ void __launch_bounds__(256,2) dense_gemm(
    const float* __restrict__ Ain, const float* __restrict__ B,
    float* __restrict__ Cext, int M, int N, int K)
{
    const float* A = (MODE==2) ? (const float*)g_ybuf : Ain;
    float*       C = (MODE==2) ? Cext : (float*)g_ybuf;

    __shared__ float As[16][132];
    __shared__ float Bs[16][132];
    const int tid = threadIdx.x;
    const int mb = blockIdx.y*128;
    const int nb = blockIdx.x*128;
    const int tx = tid & 15, ty = tid >> 4;

    const int ar0 = tid >> 2, ar1 = ar0 + 64;
    const int ak  = (tid & 3) * 4;
    const int br0 = tid >> 5, br1 = br0 + 8;
    const int bc  = (tid & 31) * 4;

    const float* Ap0 = A + (size_t)(mb+ar0)*K + ak;
    const float* Ap1 = A + (size_t)(mb+ar1)*K + ak;
    const float* Bp0 = B + (size_t)br0*N + nb + bc;
    const float* Bp1 = B + (size_t)br1*N + nb + bc;

    float acc[8][8] = {};

    for (int k0 = 0; k0 < K; k0 += 16) {
        float4 a0 = *(const float4*)(Ap0 + k0);
        float4 a1 = *(const float4*)(Ap1 + k0);
        float4 b0 = *(const float4*)(Bp0 + (size_t)k0*N);
        float4 b1 = *(const float4*)(Bp1 + (size_t)k0*N);
        As[ak+0][ar0]=a0.x; As[ak+1][ar0]=a0.y; As[ak+2][ar0]=a0.z; As[ak+3][ar0]=a0.w;
        As[ak+0][ar1]=a1.x; As[ak+1][ar1]=a1.y; As[ak+2][ar1]=a1.z; As[ak+3][ar1]=a1.w;
        *(float4*)&Bs[br0][bc] = b0;
        *(float4*)&Bs[br1][bc] = b1;
        __syncthreads();
        #pragma unroll
        for (int kk = 0; kk < 16; kk++) {
            float af[8], bf[8];
            *(float4*)(af  ) = *(const float4*)&As[kk][ty*8];
            *(float4*)(af+4) = *(const float4*)&As[kk][ty*8+4];
            *(float4*)(bf  ) = *(const float4*)&Bs[kk][tx*8];
            *(float4*)(bf+4) = *(const float4*)&Bs[kk][tx*8+4];
            #pragma unroll
            for (int i = 0; i < 8; i++)
                #pragma unroll
                for (int j = 0; j < 8; j++)
                    acc[i][j] = fmaf(af[i], bf[j], acc[i][j]);
        }
        __syncthreads();
    }

    #pragma unroll
    for (int i = 0; i < 8; i++) {
        int row = mb + ty*8 + i;
        float rs = (MODE==2) ? g_sig[row] : 0.f;
        float* cp = C + (size_t)row*N + nb + tx*8;
        #pragma unroll
        for (int j = 0; j < 8; j++) {
            if (MODE == 0) {
                cp[j] = acc[i][j];
            } else if (MODE == 1) {
                float g = cp[j];
                cp[j] = g / (1.f + __expf(-g)) * acc[i][j];
            } else {
                cp[j] = rs * acc[i][j];
            }
        }
    }
}

// ============================ grouped MoE GEMM ============================
// MODE 0: g_hbuf[pos] = x[tok] @ w_gate[e]
// MODE 1: g_hbuf[pos] = silu(g_hbuf[pos]) * (x[tok] @ w_up[e])
// MODE 2: g_pbuf[pos] = g_hbuf[pos] @ w_down[e]
template<int MODE>
__global__ void __launch_bounds__(256,2) moe_gemm(
    const float* __restrict__ X, const float* __restrict__ W)
{
    constexpr int K = (MODE==2) ? FF : HH;
    constexpr int N = (MODE==2) ? HH : FF;
    const int e   = blockIdx.z;
    const int off = g_off[e];
    const int cnt = g_off[e+1] - off;
    const int mb  = blockIdx.y*128;
    if (mb >= cnt) return;
    const int nb  = blockIdx.x*128;
    const float* B = W + (size_t)e*K*N;

    __shared__ float As[16][132];
    __shared__ float Bs[16][132];
    const int tid = threadIdx.x;
    const int tx = tid & 15, ty = tid >> 4;
    const int ar0 = tid >> 2, ar1 = ar0 + 64;
    const int ak  = (tid & 3) * 4;
    const int br0 = tid >> 5, br1 = br0 + 8;
    const int bc  = (tid & 31) * 4;

    const bool v0 = (mb+ar0) < cnt;
    const bool v1 = (mb+ar1) < cnt;
    const float* Ap0;
    const float* Ap1;
    if (MODE < 2) {
        Ap0 = v0 ? X + (size_t)g_tok[off+mb+ar0]*HH + ak : X;
        Ap1 = v1 ? X + (size_t)g_tok[off+mb+ar1]*HH + ak : X;
    } else {
        Ap0 = g_hbuf + (size_t)(off+mb+ar0)*FF + ak;
        Ap1 = g_hbuf + (size_t)(off+mb+ar1)*FF + ak;
    }
    const float* Bp0 = B + (size_t)br0*N + nb + bc;
    const float* Bp1 = B + (size_t)br1*N + nb + bc;

    float acc[8][8] = {};

    for (int k0 = 0; k0 < K; k0 += 16) {
        float4 a0 = v0 ? *(const float4*)(Ap0 + k0) : make_float4(0.f,0.f,0.f,0.f);
        float4 a1 = v1 ? *(const float4*)(Ap1 + k0) : make_float4(0.f,0.f,0.f,0.f);
        float4 b0 = *(const float4*)(Bp0 + (size_t)k0*N);
        float4 b1 = *(const float4*)(Bp1 + (size_t)k0*N);
        As[ak+0][ar0]=a0.x; As[ak+1][ar0]=a0.y; As[ak+2][ar0]=a0.z; As[ak+3][ar0]=a0.w;
        As[ak+0][ar1]=a1.x; As[ak+1][ar1]=a1.y; As[ak+2][ar1]=a1.z; As[ak+3][ar1]=a1.w;
        *(float4*)&Bs[br0][bc] = b0;
        *(float4*)&Bs[br1][bc] = b1;
        __syncthreads();
        #pragma unroll
        for (int kk = 0; kk < 16; kk++) {
            float af[8], bf[8];
            *(float4*)(af  ) = *(const float4*)&As[kk][ty*8];
            *(float4*)(af+4) = *(const float4*)&As[kk][ty*8+4];
            *(float4*)(bf  ) = *(const float4*)&Bs[kk][tx*8];
            *(float4*)(bf+4) = *(const float4*)&Bs[kk][tx*8+4];
            #pragma unroll
            for (int i = 0; i < 8; i++)
                #pragma unroll
                for (int j = 0; j < 8; j++)
                    acc[i][j] = fmaf(af[i], bf[j], acc[i][j]);
        }
        __syncthreads();
    }

    #pragma unroll
    for (int i = 0; i < 8; i++) {
        int rl = mb + ty*8 + i;
        if (rl < cnt) {
            if (MODE < 2) {
                float* cp = g_hbuf + (size_t)(off+rl)*FF + nb + tx*8;
                #pragma unroll
                for (int j = 0; j < 8; j++) {
                    if (MODE == 0) cp[j] = acc[i][j];
                    else { float g = cp[j]; cp[j] = g / (1.f + __expf(-g)) * acc[i][j]; }
                }
            } else {
                float* cp = g_pbuf + (size_t)(off+rl)*HH + nb + tx*8;
                #pragma unroll
                for (int j = 0; j < 8; j++) cp[j] = acc[i][j];
            }
        }
    }
}

// ============================ final combine (deterministic) ============================
__global__ void combine_kernel(float* __restrict__ out)
{
    int t = blockIdx.x, tid = threadIdx.x;   // 256 threads
    int p0 = g_pos[t*4+0], p1 = g_pos[t*4+1], p2 = g_pos[t*4+2], p3 = g_pos[t*4+3];
    float w0 = g_topw[t*4+0], w1 = g_topw[t*4+1], w2 = g_topw[t*4+2], w3 = g_topw[t*4+3];
    const float* r0 = g_pbuf + (size_t)p0*HH;
    const float* r1 = g_pbuf + (size_t)p1*HH;
    const float* r2 = g_pbuf + (size_t)p2*HH;
    const float* r3 = g_pbuf + (size_t)p3*HH;
    for (int c = tid; c < HH; c += 256) {
        float v = out[(size_t)t*HH + c];
        v = fmaf(w0, r0[c], v);
        v = fmaf(w1, r1[c], v);
        v = fmaf(w2, r2[c], v);
        v = fmaf(w3, r3[c], v);
        out[(size_t)t*HH + c] = v;
    }
}

// ============================ launch ============================
extern "C" void kernel_launch(void* const* d_in, const int* in_sizes, int n_in,
                              void* d_out, int out_size)
{
    const float* x   = (const float*)d_in[0];  // [T,H]
    const float* rw  = (const float*)d_in[1];  // [H,E]
    const float* wg  = (const float*)d_in[2];  // [E,H,F]
    const float* wu  = (const float*)d_in[3];  // [E,H,F]
    const float* wd  = (const float*)d_in[4];  // [E,F,H]
    const float* shg = (const float*)d_in[5];  // [H,SS]
    const float* shu = (const float*)d_in[6];  // [H,SS]
    const float* shd = (const float*)d_in[7];  // [SS,H]
    const float* seg = (const float*)d_in[8];  // [H,1]
    float* out = (float*)d_out;                // [T,H]
    (void)in_sizes; (void)n_in; (void)out_size;

    // routing
    router_kernel<<<TT, 64>>>(x, rw, seg);
    build1_kernel<<<1, 256>>>();
    build2_kernel<<<32, 256>>>();

    // shared expert: gate, up+silu-mul, down (+sigmoid expert gate) -> out
    dense_gemm<0><<<dim3(SS/128, TT/128), 256>>>(x, shg, nullptr, TT, SS, HH);
    dense_gemm<1><<<dim3(SS/128, TT/128), 256>>>(x, shu, nullptr, TT, SS, HH);
    dense_gemm<2><<<dim3(HH/128, TT/128), 256>>>(nullptr, shd, out, TT, HH, SS);

    // MoE experts: gate, up+silu-mul, down -> pair buffer
    moe_gemm<0><<<dim3(FF/128, TT/128, EE), 256>>>(x, wg);
    moe_gemm<1><<<dim3(FF/128, TT/128, EE), 256>>>(x, wu);
    moe_gemm<2><<<dim3(HH/128, TT/128, EE), 256>>>(x, wd);

    // out += sum_k topw * pair contribution
    combine_kernel<<<TT, 256>>>(out);
}

// round 2
// speedup vs baseline: 1.2948x; 1.2948x over previous
#include <cuda_runtime.h>
#include <cuda_bf16.h>
#include <math.h>
#include <stdint.h>

#define TT 2048     // tokens
#define HH 2048     // hidden
#define FF 1408     // moe intermediate
#define EE 60       // experts
#define TK 4        // top-k
#define SS 5632     // shared intermediate
#define NP (TT*TK)  // 8192 routed pairs

// ---- scratch (device globals: allocation-free rule) ----
__device__ float g_ybuf[(size_t)TT*SS];   // shared-expert gate/act buffer [T,SS]
__device__ float g_hbuf[(size_t)NP*FF];   // moe per-pair hidden [NP,FF]
__device__ float g_pbuf[(size_t)NP*HH];   // moe per-pair down output [NP,HH]
__device__ float g_topw[NP];
__device__ int   g_topidx[NP];
__device__ float g_sig[TT];
__device__ int   g_off[EE+1];
__device__ int   g_tok[NP];               // position -> token
__device__ int   g_pos[NP];               // pair -> position

// ============================ helpers ============================
__device__ __forceinline__ void split_pack(float x, float y, uint32_t &whi, uint32_t &wlo)
{
    __nv_bfloat16 hx = __float2bfloat16(x);
    __nv_bfloat16 hy = __float2bfloat16(y);
    float rx = x - __bfloat162float(hx);
    float ry = y - __bfloat162float(hy);
    __nv_bfloat16 lx = __float2bfloat16(rx);
    __nv_bfloat16 ly = __float2bfloat16(ry);
    whi = (uint32_t)__bfloat16_as_ushort(hx) | ((uint32_t)__bfloat16_as_ushort(hy) << 16);
    wlo = (uint32_t)__bfloat16_as_ushort(lx) | ((uint32_t)__bfloat16_as_ushort(ly) << 16);
}

__device__ __forceinline__ void mma16816(float c[4], const uint32_t a[4], const uint32_t b[2])
{
    asm volatile(
        "mma.sync.aligned.m16n8k16.row.col.f32.bf16.bf16.f32 "
        "{%0,%1,%2,%3}, {%4,%5,%6,%7}, {%8,%9}, {%0,%1,%2,%3};\n"
        : "+f"(c[0]), "+f"(c[1]), "+f"(c[2]), "+f"(c[3])
        : "r"(a[0]), "r"(a[1]), "r"(a[2]), "r"(a[3]), "r"(b[0]), "r"(b[1]));
}

__device__ __forceinline__ float silu_f(float g) { return g / (1.f + __expf(-g)); }

// ============================ router ============================
__global__ void router_kernel(const float* __restrict__ x,
                              const float* __restrict__ rw,
                              const float* __restrict__ seg)
{
    int t = blockIdx.x;
    int tid = threadIdx.x;              // 64 threads
    __shared__ float xs[HH];
    __shared__ float lg[EE];
    __shared__ float red[64];
    const float* xr = x + (size_t)t*HH;
    for (int i = tid; i < HH; i += 64) xs[i] = xr[i];
    __syncthreads();
    if (tid < EE) {
        float a=0.f,b=0.f,c=0.f,d=0.f;
        for (int k = 0; k < HH; k += 4) {
            a = fmaf(xs[k+0], rw[(size_t)(k+0)*EE + tid], a);
            b = fmaf(xs[k+1], rw[(size_t)(k+1)*EE + tid], b);
            c = fmaf(xs[k+2], rw[(size_t)(k+2)*EE + tid], c);
            d = fmaf(xs[k+3], rw[(size_t)(k+3)*EE + tid], d);
        }
        lg[tid] = (a+b)+(c+d);
    }
    float p = 0.f;
    for (int k = tid; k < HH; k += 64) p = fmaf(xs[k], seg[k], p);
    red[tid] = p;
    __syncthreads();
    if (tid == 0) {
        float m = lg[0];
        for (int e = 1; e < EE; e++) m = fmaxf(m, lg[e]);
        float s = 0.f;
        for (int e = 0; e < EE; e++) { float v = __expf(lg[e]-m); lg[e] = v; s += v; }
        float inv = 1.f/s;
        for (int e = 0; e < EE; e++) lg[e] *= inv;
        for (int j = 0; j < TK; j++) {
            int bi = 0; float bv = lg[0];
            for (int e = 1; e < EE; e++) { if (lg[e] > bv) { bv = lg[e]; bi = e; } }
            g_topidx[t*TK+j] = bi;
            g_topw[t*TK+j]  = bv;
            lg[bi] = -1.f;
        }
        float ss = 0.f;
        for (int i = 0; i < 64; i++) ss += red[i];
        g_sig[t] = 1.f/(1.f + __expf(-ss));
    }
}

// ================= routing tables =================
__global__ void build1_kernel()
{
    __shared__ int cnt[EE];
    int tid = threadIdx.x;              // 256
    if (tid < EE) cnt[tid] = 0;
    __syncthreads();
    for (int p = tid; p < NP; p += 256) atomicAdd(&cnt[g_topidx[p]], 1);
    __syncthreads();
    if (tid == 0) {
        int s = 0;
        for (int e = 0; e < EE; e++) { g_off[e] = s; s += cnt[e]; }
        g_off[EE] = s;
    }
}

__global__ void build2_kernel()
{
    __shared__ int sidx[NP];            // 32 KB
    int tid = threadIdx.x;              // 256, grid 32 -> one thread per pair
    for (int i = tid; i < NP; i += 256) sidx[i] = g_topidx[i];
    __syncthreads();
    int p = blockIdx.x*256 + tid;
    int e = sidx[p];
    int r = 0;
    for (int q = 0; q < p; q++) r += (sidx[q] == e);   // deterministic rank
    int pos = g_off[e] + r;
    g_tok[pos] = p >> 2;
    g_pos[p]   = pos;
}

// ============================ dense tensor-core GEMM (shared expert) ============================
// MODE 0: g_ybuf = x @ shg                         [T,SS]
// MODE 1: g_ybuf = silu(g_ybuf) * (x @ shu)
// MODE 2: out    = sig[row] * (g_ybuf @ shd)       [T,HH]
template<int MODE>
__global__ void __launch_bounds__(256,1) dense_tc(const float* __restrict__ Ain,
                                                  const float* __restrict__ B,
                                                  float* __restrict__ Cext)
{
    constexpr int N = (MODE==2) ? HH : SS;
    constexpr int K = (MODE==2) ? SS : HH;
    constexpr int NIT = K/16;
    const float* A = (MODE==2) ? (const float*)g_ybuf : Ain;

    __shared__ uint32_t As[2][2][128*9];   // [buf][hi/lo][row*9 + kpair]
    __shared__ uint32_t Bs[2][2][8*136];   // [buf][hi/lo][kpair*136 + n]

    const int tid  = threadIdx.x;
    const int lane = tid & 31;
    const int w    = tid >> 5;
    const int wm   = (w & 1) * 64;
    const int wn   = (w >> 1) * 32;
    const int r    = lane >> 2;
    const int q    = lane & 3;
    const int mb   = blockIdx.y * 128;
    const int nb   = blockIdx.x * 128;

    // A gmem mapping: kpair ak2, rows arb + 32p
    const int ak2 = tid & 7;
    const int arb = tid >> 3;
    const float* pa[4];
    #pragma unroll
    for (int p = 0; p < 4; p++)
        pa[p] = A + (size_t)(mb + arb + 32*p)*K + ak2*2;

    // B gmem mapping: column bn, k rows bkh*8 .. +7
    const int bn  = tid & 127;
    const int bkh = tid >> 7;
    const float* pb = B + (size_t)(bkh*8)*N + nb + bn;

    float2 av[4];
    float  bv[8];
    #pragma unroll
    for (int p = 0; p < 4; p++) av[p] = *(const float2*)(pa[p]);
    #pragma unroll
    for (int t = 0; t < 8; t++) bv[t] = pb[(size_t)t*N];

    #pragma unroll
    for (int p = 0; p < 4; p++) {
        uint32_t whi, wlo; split_pack(av[p].x, av[p].y, whi, wlo);
        As[0][0][(arb+32*p)*9 + ak2] = whi;
        As[0][1][(arb+32*p)*9 + ak2] = wlo;
    }
    #pragma unroll
    for (int t2 = 0; t2 < 4; t2++) {
        uint32_t whi, wlo; split_pack(bv[2*t2], bv[2*t2+1], whi, wlo);
        int qg = bkh*4 + t2;
        Bs[0][0][qg*136 + bn] = whi;
        Bs[0][1][qg*136 + bn] = wlo;
    }
    __syncthreads();

    float acc[4][4][4] = {};
    int buf = 0;

    for (int it = 0; it < NIT; ++it) {
        if (it + 1 < NIT) {
            int k0 = (it+1)*16;
            #pragma unroll
            for (int p = 0; p < 4; p++) av[p] = *(const float2*)(pa[p] + k0);
            #pragma unroll
            for (int t = 0; t < 8; t++) bv[t] = pb[(size_t)(k0+t)*N];
        }
        uint32_t bh[4][2], bl[4][2];
        #pragma unroll
        for (int j = 0; j < 4; j++) {
            int col = wn + j*8 + r;
            bh[j][0] = Bs[buf][0][q*136 + col];
            bh[j][1] = Bs[buf][0][(q+4)*136 + col];
            bl[j][0] = Bs[buf][1][q*136 + col];
            bl[j][1] = Bs[buf][1][(q+4)*136 + col];
        }
        #pragma unroll
        for (int i = 0; i < 4; i++) {
            int row = wm + i*16 + r;
            uint32_t ah[4], al[4];
            ah[0] = As[buf][0][row*9 + q];     ah[1] = As[buf][0][(row+8)*9 + q];
            ah[2] = As[buf][0][row*9 + q+4];   ah[3] = As[buf][0][(row+8)*9 + q+4];
            al[0] = As[buf][1][row*9 + q];     al[1] = As[buf][1][(row+8)*9 + q];
            al[2] = As[buf][1][row*9 + q+4];   al[3] = As[buf][1][(row+8)*9 + q+4];
            #pragma unroll
            for (int j = 0; j < 4; j++) {
                mma16816(acc[i][j], ah, bh[j]);
                mma16816(acc[i][j], al, bh[j]);
                mma16816(acc[i][j], ah, bl[j]);
            }
        }
        if (it + 1 < NIT) {
            int nbuf = buf ^ 1;
            #pragma unroll
            for (int p = 0; p < 4; p++) {
                uint32_t whi, wlo; split_pack(av[p].x, av[p].y, whi, wlo);
                As[nbuf][0][(arb+32*p)*9 + ak2] = whi;
                As[nbuf][1][(arb+32*p)*9 + ak2] = wlo;
            }
            #pragma unroll
            for (int t2 = 0; t2 < 4; t2++) {
                uint32_t whi, wlo; split_pack(bv[2*t2], bv[2*t2+1], whi, wlo);
                int qg = bkh*4 + t2;
                Bs[nbuf][0][qg*136 + bn] = whi;
                Bs[nbuf][1][qg*136 + bn] = wlo;
            }
        }
        __syncthreads();
        buf ^= 1;
    }

    #pragma unroll
    for (int i = 0; i < 4; i++) {
        #pragma unroll
        for (int j = 0; j < 4; j++) {
            int row0 = mb + wm + i*16 + r;
            int row1 = row0 + 8;
            int col  = nb + wn + j*8 + q*2;
            if (MODE == 0) {
                *(float2*)&g_ybuf[(size_t)row0*SS + col] = make_float2(acc[i][j][0], acc[i][j][1]);
                *(float2*)&g_ybuf[(size_t)row1*SS + col] = make_float2(acc[i][j][2], acc[i][j][3]);
            } else if (MODE == 1) {
                float2 g0 = *(float2*)&g_ybuf[(size_t)row0*SS + col];
                float2 g1 = *(float2*)&g_ybuf[(size_t)row1*SS + col];
                *(float2*)&g_ybuf[(size_t)row0*SS + col] =
                    make_float2(silu_f(g0.x)*acc[i][j][0], silu_f(g0.y)*acc[i][j][1]);
                *(float2*)&g_ybuf[(size_t)row1*SS + col] =
                    make_float2(silu_f(g1.x)*acc[i][j][2], silu_f(g1.y)*acc[i][j][3]);
            } else {
                float s0 = g_sig[row0], s1 = g_sig[row1];
                *(float2*)&Cext[(size_t)row0*HH + col] = make_float2(s0*acc[i][j][0], s0*acc[i][j][1]);
                *(float2*)&Cext[(size_t)row1*HH + col] = make_float2(s1*acc[i][j][2], s1*acc[i][j][3]);
            }
        }
    }
}

// ============================ grouped MoE tensor-core GEMM ============================
// MODE 0: g_hbuf[pos] = x[tok] @ w_gate[e]
// MODE 1: g_hbuf[pos] = silu(g_hbuf[pos]) * (x[tok] @ w_up[e])
// MODE 2: g_pbuf[pos] = g_hbuf[pos] @ w_down[e]
template<int MODE>
__global__ void __launch_bounds__(256,1) moe_tc(const float* __restrict__ X,
                                                const float* __restrict__ W)
{
    constexpr int K = (MODE==2) ? FF : HH;
    constexpr int N = (MODE==2) ? HH : FF;
    constexpr int NIT = K/16;
    const int e   = blockIdx.z;
    const int off = g_off[e];
    const int cnt = g_off[e+1] - off;
    const int mb  = blockIdx.y * 128;
    if (mb >= cnt) return;
    const int nb  = blockIdx.x * 128;
    const float* Bw = W + (size_t)e*K*N;

    __shared__ uint32_t As[2][2][128*9];
    __shared__ uint32_t Bs[2][2][8*136];

    const int tid  = threadIdx.x;
    const int lane = tid & 31;
    const int w    = tid >> 5;
    const int wm   = (w & 1) * 64;
    const int wn   = (w >> 1) * 32;
    const int r    = lane >> 2;
    const int q    = lane & 3;

    const int ak2 = tid & 7;
    const int arb = tid >> 3;
    const float* pa[4];
    #pragma unroll
    for (int p = 0; p < 4; p++) {
        int rl = mb + arb + 32*p;
        bool va = rl < cnt;
        if (MODE < 2) {
            int tok = va ? g_tok[off + rl] : 0;
            pa[p] = X + (size_t)tok*HH + ak2*2;
        } else {
            size_t idx = va ? (size_t)(off + rl) : 0;
            pa[p] = g_hbuf + idx*FF + ak2*2;
        }
    }

    const int bn  = tid & 127;
    const int bkh = tid >> 7;
    const float* pb = Bw + (size_t)(bkh*8)*N + nb + bn;

    float2 av[4];
    float  bv[8];
    #pragma unroll
    for (int p = 0; p < 4; p++) av[p] = *(const float2*)(pa[p]);
    #pragma unroll
    for (int t = 0; t < 8; t++) bv[t] = pb[(size_t)t*N];

    #pragma unroll
    for (int p = 0; p < 4; p++) {
        uint32_t whi, wlo; split_pack(av[p].x, av[p].y, whi, wlo);
        As[0][0][(arb+32*p)*9 + ak2] = whi;
        As[0][1][(arb+32*p)*9 + ak2] = wlo;
    }
    #pragma unroll
    for (int t2 = 0; t2 < 4; t2++) {
        uint32_t whi, wlo; split_pack(bv[2*t2], bv[2*t2+1], whi, wlo);
        int qg = bkh*4 + t2;
        Bs[0][0][qg*136 + bn] = whi;
        Bs[0][1][qg*136 + bn] = wlo;
    }
    __syncthreads();

    float acc[4][4][4] = {};
    int buf = 0;

    for (int it = 0; it < NIT; ++it) {
        if (it + 1 < NIT) {
            int k0 = (it+1)*16;
            #pragma unroll
            for (int p = 0; p < 4; p++) av[p] = *(const float2*)(pa[p] + k0);
            #pragma unroll
            for (int t = 0; t < 8; t++) bv[t] = pb[(size_t)(k0+t)*N];
        }
        uint32_t bh[4][2], bl[4][2];
        #pragma unroll
        for (int j = 0; j < 4; j++) {
            int col = wn + j*8 + r;
            bh[j][0] = Bs[buf][0][q*136 + col];
            bh[j][1] = Bs[buf][0][(q+4)*136 + col];
            bl[j][0] = Bs[buf][1][q*136 + col];
            bl[j][1] = Bs[buf][1][(q+4)*136 + col];
        }
        #pragma unroll
        for (int i = 0; i < 4; i++) {
            int row = wm + i*16 + r;
            uint32_t ah[4], al[4];
            ah[0] = As[buf][0][row*9 + q];     ah[1] = As[buf][0][(row+8)*9 + q];
            ah[2] = As[buf][0][row*9 + q+4];   ah[3] = As[buf][0][(row+8)*9 + q+4];
            al[0] = As[buf][1][row*9 + q];     al[1] = As[buf][1][(row+8)*9 + q];
            al[2] = As[buf][1][row*9 + q+4];   al[3] = As[buf][1][(row+8)*9 + q+4];
            #pragma unroll
            for (int j = 0; j < 4; j++) {
                mma16816(acc[i][j], ah, bh[j]);
                mma16816(acc[i][j], al, bh[j]);
                mma16816(acc[i][j], ah, bl[j]);
            }
        }
        if (it + 1 < NIT) {
            int nbuf = buf ^ 1;
            #pragma unroll
            for (int p = 0; p < 4; p++) {
                uint32_t whi, wlo; split_pack(av[p].x, av[p].y, whi, wlo);
                As[nbuf][0][(arb+32*p)*9 + ak2] = whi;
                As[nbuf][1][(arb+32*p)*9 + ak2] = wlo;
            }
            #pragma unroll
            for (int t2 = 0; t2 < 4; t2++) {
                uint32_t whi, wlo; split_pack(bv[2*t2], bv[2*t2+1], whi, wlo);
                int qg = bkh*4 + t2;
                Bs[nbuf][0][qg*136 + bn] = whi;
                Bs[nbuf][1][qg*136 + bn] = wlo;
            }
        }
        __syncthreads();
        buf ^= 1;
    }

    #pragma unroll
    for (int i = 0; i < 4; i++) {
        #pragma unroll
        for (int j = 0; j < 4; j++) {
            int rl0 = mb + wm + i*16 + r;
            int rl1 = rl0 + 8;
            int col = nb + wn + j*8 + q*2;
            if (MODE < 2) {
                if (rl0 < cnt) {
                    float* cp = &g_hbuf[(size_t)(off+rl0)*FF + col];
                    if (MODE == 0) *(float2*)cp = make_float2(acc[i][j][0], acc[i][j][1]);
                    else {
                        float2 g = *(float2*)cp;
                        *(float2*)cp = make_float2(silu_f(g.x)*acc[i][j][0], silu_f(g.y)*acc[i][j][1]);
                    }
                }
                if (rl1 < cnt) {
                    float* cp = &g_hbuf[(size_t)(off+rl1)*FF + col];
                    if (MODE == 0) *(float2*)cp = make_float2(acc[i][j][2], acc[i][j][3]);
                    else {
                        float2 g = *(float2*)cp;
                        *(float2*)cp = make_float2(silu_f(g.x)*acc[i][j][2], silu_f(g.y)*acc[i][j][3]);
                    }
                }
            } else {
                if (rl0 < cnt)
                    *(float2*)&g_pbuf[(size_t)(off+rl0)*HH + col] = make_float2(acc[i][j][0], acc[i][j][1]);
                if (rl1 < cnt)
                    *(float2*)&g_pbuf[(size_t)(off+rl1)*HH + col] = make_float2(acc[i][j][2], acc[i][j][3]);
            }
        }
    }
}

// ============================ final combine (deterministic) ============================
__global__ void combine_kernel(float* __restrict__ out)
{
    int t = blockIdx.x, tid = threadIdx.x;   // 256 threads
    int p0 = g_pos[t*4+0], p1 = g_pos[t*4+1], p2 = g_pos[t*4+2], p3 = g_pos[t*4+3];
    float w0 = g_topw[t*4+0], w1 = g_topw[t*4+1], w2 = g_topw[t*4+2], w3 = g_topw[t*4+3];
    const float* r0 = g_pbuf + (size_t)p0*HH;
    const float* r1 = g_pbuf + (size_t)p1*HH;
    const float* r2 = g_pbuf + (size_t)p2*HH;
    const float* r3 = g_pbuf + (size_t)p3*HH;
    for (int c = tid; c < HH; c += 256) {
        float v = out[(size_t)t*HH + c];
        v = fmaf(w0, r0[c], v);
        v = fmaf(w1, r1[c], v);
        v = fmaf(w2, r2[c], v);
        v = fmaf(w3, r3[c], v);
        out[(size_t)t*HH + c] = v;
    }
}

// ============================ launch ============================
extern "C" void kernel_launch(void* const* d_in, const int* in_sizes, int n_in,
                              void* d_out, int out_size)
{
    const float* x   = (const float*)d_in[0];  // [T,H]
    const float* rw  = (const float*)d_in[1];  // [H,E]
    const float* wg  = (const float*)d_in[2];  // [E,H,F]
    const float* wu  = (const float*)d_in[3];  // [E,H,F]
    const float* wd  = (const float*)d_in[4];  // [E,F,H]
    const float* shg = (const float*)d_in[5];  // [H,SS]
    const float* shu = (const float*)d_in[6];  // [H,SS]
    const float* shd = (const float*)d_in[7];  // [SS,H]
    const float* seg = (const float*)d_in[8];  // [H,1]
    float* out = (float*)d_out;                // [T,H]
    (void)in_sizes; (void)n_in; (void)out_size;

    // routing
    router_kernel<<<TT, 64>>>(x, rw, seg);
    build1_kernel<<<1, 256>>>();
    build2_kernel<<<32, 256>>>();

    // shared expert: gate, up+silu-mul, down (+sigmoid expert gate) -> out
    dense_tc<0><<<dim3(SS/128, TT/128), 256>>>(x, shg, nullptr);
    dense_tc<1><<<dim3(SS/128, TT/128), 256>>>(x, shu, nullptr);
    dense_tc<2><<<dim3(HH/128, TT/128), 256>>>(nullptr, shd, out);

    // MoE experts: gate, up+silu-mul, down -> pair buffer
    moe_tc<0><<<dim3(FF/128, TT/128, EE), 256>>>(x, wg);
    moe_tc<1><<<dim3(FF/128, TT/128, EE), 256>>>(x, wu);
    moe_tc<2><<<dim3(HH/128, TT/128, EE), 256>>>(x, wd);

    // out += sum_k topw * pair contribution
    combine_kernel<<<TT, 256>>>(out);
}

// round 4
// speedup vs baseline: 2.4440x; 1.8875x over previous
#include <cuda_runtime.h>
#include <cuda_fp16.h>
#include <stdint.h>
#include <math.h>

#define TT 2048     // tokens
#define HH 2048     // hidden
#define FF 1408     // moe intermediate
#define EE 60       // experts
#define TK 4        // top-k
#define SS 5632     // shared intermediate
#define NP (TT*TK)  // routed pairs

// ---- scratch ----
__device__ float g_ybuf[(size_t)TT*SS];
__device__ float g_hbuf[(size_t)NP*FF];
__device__ float g_pbuf[(size_t)NP*HH];
__device__ float g_topw[NP];
__device__ int   g_topidx[NP];
__device__ float g_sig[TT];
__device__ int   g_off[EE+1];
__device__ int   g_tok[NP];
__device__ int   g_pos[NP];

// ============================ helpers ============================
__device__ __forceinline__ uint32_t smem_u32(const void* p) {
    uint32_t a;
    asm("{ .reg .u64 t; cvta.to.shared.u64 t, %1; cvt.u32.u64 %0, t; }" : "=r"(a) : "l"(p));
    return a;
}
__device__ __forceinline__ void ldsm4(uint32_t r[4], uint32_t addr) {
    asm volatile("ldmatrix.sync.aligned.m8n8.x4.shared.b16 {%0,%1,%2,%3}, [%4];"
        : "=r"(r[0]), "=r"(r[1]), "=r"(r[2]), "=r"(r[3]) : "r"(addr));
}
__device__ __forceinline__ void ldsm4t(uint32_t r[4], uint32_t addr) {
    asm volatile("ldmatrix.sync.aligned.m8n8.x4.trans.shared.b16 {%0,%1,%2,%3}, [%4];"
        : "=r"(r[0]), "=r"(r[1]), "=r"(r[2]), "=r"(r[3]) : "r"(addr));
}
__device__ __forceinline__ void mma_f16(float c[4], const uint32_t a[4], uint32_t b0, uint32_t b1) {
    asm volatile(
        "mma.sync.aligned.m16n8k16.row.col.f32.f16.f16.f32 "
        "{%0,%1,%2,%3}, {%4,%5,%6,%7}, {%8,%9}, {%0,%1,%2,%3};\n"
        : "+f"(c[0]), "+f"(c[1]), "+f"(c[2]), "+f"(c[3])
        : "r"(a[0]), "r"(a[1]), "r"(a[2]), "r"(a[3]), "r"(b0), "r"(b1));
}
__device__ __forceinline__ uint32_t pack_h2(__half a, __half b) {
    __half2 h = __halves2half2(a, b);
    return *(uint32_t*)&h;
}
__device__ __forceinline__ float silu_f(float g) { return g / (1.f + __expf(-g)); }

// ============================ router ============================
__global__ void router_kernel(const float* __restrict__ x,
                              const float* __restrict__ rw,
                              const float* __restrict__ seg)
{
    int t = blockIdx.x;
    int tid = threadIdx.x;              // 64 threads
    __shared__ float xs[HH];
    __shared__ float lg[EE];
    __shared__ float red[64];
    const float* xr = x + (size_t)t*HH;
    for (int i = tid; i < HH; i += 64) xs[i] = xr[i];
    __syncthreads();
    if (tid < EE) {
        float a=0.f,b=0.f,c=0.f,d=0.f;
        for (int k = 0; k < HH; k += 4) {
            a = fmaf(xs[k+0], rw[(size_t)(k+0)*EE + tid], a);
            b = fmaf(xs[k+1], rw[(size_t)(k+1)*EE + tid], b);
            c = fmaf(xs[k+2], rw[(size_t)(k+2)*EE + tid], c);
            d = fmaf(xs[k+3], rw[(size_t)(k+3)*EE + tid], d);
        }
        lg[tid] = (a+b)+(c+d);
    }
    float p = 0.f;
    for (int k = tid; k < HH; k += 64) p = fmaf(xs[k], seg[k], p);
    red[tid] = p;
    __syncthreads();
    if (tid == 0) {
        float m = lg[0];
        for (int e = 1; e < EE; e++) m = fmaxf(m, lg[e]);
        float s = 0.f;
        for (int e = 0; e < EE; e++) { float v = __expf(lg[e]-m); lg[e] = v; s += v; }
        float inv = 1.f/s;
        for (int e = 0; e < EE; e++) lg[e] *= inv;
        for (int j = 0; j < TK; j++) {
            int bi = 0; float bv = lg[0];
            for (int e = 1; e < EE; e++) { if (lg[e] > bv) { bv = lg[e]; bi = e; } }
            g_topidx[t*TK+j] = bi;
            g_topw[t*TK+j]  = bv;
            lg[bi] = -1.f;
        }
        float ss = 0.f;
        for (int i = 0; i < 64; i++) ss += red[i];
        g_sig[t] = 1.f/(1.f + __expf(-ss));
    }
}

__global__ void build1_kernel()
{
    __shared__ int cnt[EE];
    int tid = threadIdx.x;              // 256
    if (tid < EE) cnt[tid] = 0;
    __syncthreads();
    for (int p = tid; p < NP; p += 256) atomicAdd(&cnt[g_topidx[p]], 1);
    __syncthreads();
    if (tid == 0) {
        int s = 0;
        for (int e = 0; e < EE; e++) { g_off[e] = s; s += cnt[e]; }
        g_off[EE] = s;
    }
}

__global__ void build2_kernel()
{
    __shared__ int sidx[NP];            // 32 KB
    int tid = threadIdx.x;              // 256, grid 32
    for (int i = tid; i < NP; i += 256) sidx[i] = g_topidx[i];
    __syncthreads();
    int p = blockIdx.x*256 + tid;
    int e = sidx[p];
    int r = 0;
    for (int q = 0; q < p; q++) r += (sidx[q] == e);
    int pos = g_off[e] + r;
    g_tok[pos] = p >> 2;
    g_pos[p]   = pos;
}

// ============================ HMMA GEMM ============================
// CTA tile 128x128, BK=32, fp16x2 split on A (hi/lo), B single fp16.
// smem stage: Ahi [128][40]h (10240B) | Alo (10240B) | B [32][136]h (8704B)
#define AHI 0
#define ALO 10240
#define BOF 20480
#define STG 29184
#define SMEM_BYTES (2*STG)

// stage-store: convert regs -> fp16 and write to smem buffer
__device__ __forceinline__ void stage_store(char* base, const float4 av[4], const float4 bv[4],
                                            int ar, int ah, int bk, int bn)
{
    uint32_t wh[8], wl[8], wb[8];
    #pragma unroll
    for (int i = 0; i < 4; i++) {
        float x0 = av[i].x, x1 = av[i].y, x2 = av[i].z, x3 = av[i].w;
        __half h0 = __float2half_rn(x0), h1 = __float2half_rn(x1);
        __half h2 = __float2half_rn(x2), h3 = __float2half_rn(x3);
        wh[2*i]   = pack_h2(h0, h1);
        wh[2*i+1] = pack_h2(h2, h3);
        __half l0 = __float2half_rn(x0 - __half2float(h0));
        __half l1 = __float2half_rn(x1 - __half2float(h1));
        __half l2 = __float2half_rn(x2 - __half2float(h2));
        __half l3 = __float2half_rn(x3 - __half2float(h3));
        wl[2*i]   = pack_h2(l0, l1);
        wl[2*i+1] = pack_h2(l2, l3);
        float y0 = bv[i].x, y1 = bv[i].y, y2 = bv[i].z, y3 = bv[i].w;
        wb[2*i]   = pack_h2(__float2half_rn(y0), __float2half_rn(y1));
        wb[2*i+1] = pack_h2(__float2half_rn(y2), __float2half_rn(y3));
    }
    char* pa = base + AHI + ar*80 + ah*2;
    *(uint4*)(pa)      = make_uint4(wh[0], wh[1], wh[2], wh[3]);
    *(uint4*)(pa + 16) = make_uint4(wh[4], wh[5], wh[6], wh[7]);
    char* pl = base + ALO + ar*80 + ah*2;
    *(uint4*)(pl)      = make_uint4(wl[0], wl[1], wl[2], wl[3]);
    *(uint4*)(pl + 16) = make_uint4(wl[4], wl[5], wl[6], wl[7]);
    char* pb = base + BOF + bk*272 + bn*2;
    *(uint4*)(pb)      = make_uint4(wb[0], wb[1], wb[2], wb[3]);
    *(uint4*)(pb + 16) = make_uint4(wb[4], wb[5], wb[6], wb[7]);
}

// MOE=false: MODE0 ybuf=x@shg | MODE1 ybuf=silu(ybuf)*(x@shu) | MODE2 out=sig*(ybuf@shd)
// MOE=true : MODE0 hbuf=x[tok]@wg[e] | MODE1 hbuf=silu(hbuf)*(x[tok]@wu[e]) | MODE2 pbuf=hbuf@wd[e]
template<int MODE, bool MOE>
__global__ void __launch_bounds__(256,1) gemm_hmma(const float* __restrict__ Aex,
                                                   const float* __restrict__ Bw,
                                                   float* __restrict__ Cex)
{
    constexpr int K = MOE ? ((MODE==2) ? FF : HH) : ((MODE==2) ? SS : HH);
    constexpr int N = MOE ? ((MODE==2) ? HH : FF) : ((MODE==2) ? HH : SS);
    constexpr int NSLAB = K/32;

    extern __shared__ __align__(16) char dsm[];
    const uint32_t sb = smem_u32(dsm);

    const int tid = threadIdx.x, lane = tid & 31, w = tid >> 5;
    const int wm = (w & 3)*32, wn = (w >> 2)*64;

    int e = 0, off = 0, cnt = TT;
    if (MOE) { e = blockIdx.z; off = g_off[e]; cnt = g_off[e+1] - off; }
    const int mb = blockIdx.y*128;
    if (MOE && mb >= cnt) return;
    const int nb = blockIdx.x*128;
    const float* Bp = MOE ? Bw + (size_t)e*K*N : Bw;
    const float* Abase = (!MOE && MODE==2) ? (const float*)g_ybuf
                       : ( MOE && MODE==2) ? (const float*)g_hbuf
                       : Aex;

    // fill mappings
    const int ar = tid >> 1, ah = (tid & 1)*16;
    const float* aptr;
    {
        int rl = mb + ar;
        if (MOE) {
            int rc = (rl < cnt) ? rl : (cnt - 1);
            if (MODE < 2) aptr = Abase + (size_t)g_tok[off + rc]*HH + ah;
            else          aptr = Abase + (size_t)(off + rc)*FF + ah;
        } else {
            aptr = Abase + (size_t)rl*K + ah;
        }
    }
    const int bk = tid >> 3, bn = (tid & 7)*16;
    const float* bptr = Bp + (size_t)bk*N + nb + bn;

    // fragment lane addresses (byte offsets within a stage)
    const int lr = lane & 15, lc = lane >> 4;
    const uint32_t aoff0 = (uint32_t)(((wm + lr)*40 + lc*8)*2);
    const uint32_t aoff1 = aoff0 + 16*80;
    uint32_t boff[4];
    #pragma unroll
    for (int np = 0; np < 4; np++)
        boff[np] = (uint32_t)((lr*136 + wn + np*16 + lc*8)*2) + BOF;

    float acc[2][8][4] = {};

    // slab 0 preload + store
    float4 av[4], bv[4];
    #pragma unroll
    for (int i = 0; i < 4; i++) av[i] = *(const float4*)(aptr + i*4);
    #pragma unroll
    for (int i = 0; i < 4; i++) bv[i] = *(const float4*)(bptr + i*4);
    stage_store(dsm, av, bv, ar, ah, bk, bn);
    __syncthreads();

    for (int s = 0; s < NSLAB; s++) {
        const uint32_t sbb = sb + (uint32_t)((s & 1)*STG);
        if (s + 1 < NSLAB) {
            const float* ap = aptr + (s+1)*32;
            const float* bp = bptr + (size_t)(s+1)*32*N;
            #pragma unroll
            for (int i = 0; i < 4; i++) av[i] = *(const float4*)(ap + i*4);
            #pragma unroll
            for (int i = 0; i < 4; i++) bv[i] = *(const float4*)(bp + i*4);
        }
        #pragma unroll
        for (int ks = 0; ks < 2; ks++) {
            const uint32_t kbA = ks*32;        // 16 fp16 -> 32 bytes
            const uint32_t kbB = ks*16*272;    // 16 k-rows
            uint32_t a0h[4], a1h[4], a0l[4], a1l[4];
            ldsm4(a0h, sbb + AHI + aoff0 + kbA);
            ldsm4(a1h, sbb + AHI + aoff1 + kbA);
            ldsm4(a0l, sbb + ALO + aoff0 + kbA);
            ldsm4(a1l, sbb + ALO + aoff1 + kbA);
            #pragma unroll
            for (int np = 0; np < 4; np++) {
                uint32_t bb[4];
                ldsm4t(bb, sbb + boff[np] + kbB);
                mma_f16(acc[0][np*2],   a0h, bb[0], bb[1]);
                mma_f16(acc[0][np*2],   a0l, bb[0], bb[1]);
                mma_f16(acc[0][np*2+1], a0h, bb[2], bb[3]);
                mma_f16(acc[0][np*2+1], a0l, bb[2], bb[3]);
                mma_f16(acc[1][np*2],   a1h, bb[0], bb[1]);
                mma_f16(acc[1][np*2],   a1l, bb[0], bb[1]);
                mma_f16(acc[1][np*2+1], a1h, bb[2], bb[3]);
                mma_f16(acc[1][np*2+1], a1l, bb[2], bb[3]);
            }
        }
        if (s + 1 < NSLAB)
            stage_store(dsm + ((s+1) & 1)*STG, av, bv, ar, ah, bk, bn);
        __syncthreads();
    }

    // ---- epilogue ----
    #pragma unroll
    for (int mt = 0; mt < 2; mt++) {
        const int r0 = mb + wm + mt*16 + (lane >> 2);
        const int r1 = r0 + 8;
        const bool v0 = MOE ? (r0 < cnt) : true;
        const bool v1 = MOE ? (r1 < cnt) : true;
        #pragma unroll
        for (int nt = 0; nt < 8; nt++) {
            const int col = nb + wn + nt*8 + (lane & 3)*2;
            const float* c = acc[mt][nt];
            if (!MOE) {
                if (MODE == 0) {
                    *(float2*)&g_ybuf[(size_t)r0*SS + col] = make_float2(c[0], c[1]);
                    *(float2*)&g_ybuf[(size_t)r1*SS + col] = make_float2(c[2], c[3]);
                } else if (MODE == 1) {
                    float2 g0 = *(float2*)&g_ybuf[(size_t)r0*SS + col];
                    float2 g1 = *(float2*)&g_ybuf[(size_t)r1*SS + col];
                    *(float2*)&g_ybuf[(size_t)r0*SS + col] =
                        make_float2(silu_f(g0.x)*c[0], silu_f(g0.y)*c[1]);
                    *(float2*)&g_ybuf[(size_t)r1*SS + col] =
                        make_float2(silu_f(g1.x)*c[2], silu_f(g1.y)*c[3]);
                } else {
                    float s0 = g_sig[r0], s1 = g_sig[r1];
                    *(float2*)&Cex[(size_t)r0*HH + col] = make_float2(s0*c[0], s0*c[1]);
                    *(float2*)&Cex[(size_t)r1*HH + col] = make_float2(s1*c[2], s1*c[3]);
                }
            } else {
                if (MODE == 0) {
                    if (v0) *(float2*)&g_hbuf[(size_t)(off+r0)*FF + col] = make_float2(c[0], c[1]);
                    if (v1) *(float2*)&g_hbuf[(size_t)(off+r1)*FF + col] = make_float2(c[2], c[3]);
                } else if (MODE == 1) {
                    if (v0) {
                        float2 g = *(float2*)&g_hbuf[(size_t)(off+r0)*FF + col];
                        *(float2*)&g_hbuf[(size_t)(off+r0)*FF + col] =
                            make_float2(silu_f(g.x)*c[0], silu_f(g.y)*c[1]);
                    }
                    if (v1) {
                        float2 g = *(float2*)&g_hbuf[(size_t)(off+r1)*FF + col];
                        *(float2*)&g_hbuf[(size_t)(off+r1)*FF + col] =
                            make_float2(silu_f(g.x)*c[2], silu_f(g.y)*c[3]);
                    }
                } else {
                    if (v0) *(float2*)&g_pbuf[(size_t)(off+r0)*HH + col] = make_float2(c[0], c[1]);
                    if (v1) *(float2*)&g_pbuf[(size_t)(off+r1)*HH + col] = make_float2(c[2], c[3]);
                }
            }
        }
    }
}

// ============================ combine ============================
__global__ void combine_kernel(float* __restrict__ out)
{
    int t = blockIdx.x, tid = threadIdx.x;
    int p0 = g_pos[t*4+0], p1 = g_pos[t*4+1], p2 = g_pos[t*4+2], p3 = g_pos[t*4+3];
    float w0 = g_topw[t*4+0], w1 = g_topw[t*4+1], w2 = g_topw[t*4+2], w3 = g_topw[t*4+3];
    const float* r0 = g_pbuf + (size_t)p0*HH;
    const float* r1 = g_pbuf + (size_t)p1*HH;
    const float* r2 = g_pbuf + (size_t)p2*HH;
    const float* r3 = g_pbuf + (size_t)p3*HH;
    for (int c = tid; c < HH; c += 256) {
        float v = out[(size_t)t*HH + c];
        v = fmaf(w0, r0[c], v);
        v = fmaf(w1, r1[c], v);
        v = fmaf(w2, r2[c], v);
        v = fmaf(w3, r3[c], v);
        out[(size_t)t*HH + c] = v;
    }
}

// ============================ launch ============================
extern "C" void kernel_launch(void* const* d_in, const int* in_sizes, int n_in,
                              void* d_out, int out_size)
{
    const float* x   = (const float*)d_in[0];
    const float* rw  = (const float*)d_in[1];
    const float* wg  = (const float*)d_in[2];
    const float* wu  = (const float*)d_in[3];
    const float* wd  = (const float*)d_in[4];
    const float* shg = (const float*)d_in[5];
    const float* shu = (const float*)d_in[6];
    const float* shd = (const float*)d_in[7];
    const float* seg = (const float*)d_in[8];
    float* out = (float*)d_out;
    (void)in_sizes; (void)n_in; (void)out_size;

    cudaFuncSetAttribute(gemm_hmma<0,false>, cudaFuncAttributeMaxDynamicSharedMemorySize, SMEM_BYTES);
    cudaFuncSetAttribute(gemm_hmma<1,false>, cudaFuncAttributeMaxDynamicSharedMemorySize, SMEM_BYTES);
    cudaFuncSetAttribute(gemm_hmma<2,false>, cudaFuncAttributeMaxDynamicSharedMemorySize, SMEM_BYTES);
    cudaFuncSetAttribute(gemm_hmma<0,true>,  cudaFuncAttributeMaxDynamicSharedMemorySize, SMEM_BYTES);
    cudaFuncSetAttribute(gemm_hmma<1,true>,  cudaFuncAttributeMaxDynamicSharedMemorySize, SMEM_BYTES);
    cudaFuncSetAttribute(gemm_hmma<2,true>,  cudaFuncAttributeMaxDynamicSharedMemorySize, SMEM_BYTES);

    router_kernel<<<TT, 64>>>(x, rw, seg);
    build1_kernel<<<1, 256>>>();
    build2_kernel<<<32, 256>>>();

    // shared expert
    gemm_hmma<0,false><<<dim3(SS/128, TT/128), 256, SMEM_BYTES>>>(x, shg, nullptr);
    gemm_hmma<1,false><<<dim3(SS/128, TT/128), 256, SMEM_BYTES>>>(x, shu, nullptr);
    gemm_hmma<2,false><<<dim3(HH/128, TT/128), 256, SMEM_BYTES>>>(nullptr, shd, out);

    // MoE experts
    gemm_hmma<0,true><<<dim3(FF/128, TT/128, EE), 256, SMEM_BYTES>>>(x, wg, nullptr);
    gemm_hmma<1,true><<<dim3(FF/128, TT/128, EE), 256, SMEM_BYTES>>>(x, wu, nullptr);
    gemm_hmma<2,true><<<dim3(HH/128, TT/128, EE), 256, SMEM_BYTES>>>(nullptr, wd, nullptr);

    combine_kernel<<<TT, 256>>>(out);
}

// round 5
// speedup vs baseline: 2.5817x; 1.0563x over previous
#include <cuda_runtime.h>
#include <cuda_fp16.h>
#include <stdint.h>
#include <math.h>

#define TT 2048     // tokens
#define HH 2048     // hidden
#define FF 1408     // moe intermediate
#define EE 60       // experts
#define TK 4        // top-k
#define SS 5632     // shared intermediate
#define NP (TT*TK)  // routed pairs

// ---- scratch ----
__device__ float g_ybuf[(size_t)TT*SS];
__device__ float g_hbuf[(size_t)NP*FF];
__device__ float g_pbuf[(size_t)NP*HH];
__device__ float g_topw[NP];
__device__ int   g_topidx[NP];
__device__ float g_sig[TT];
__device__ int   g_off[EE+1];
__device__ int   g_tok[NP];
__device__ int   g_pos[NP];

// ============================ helpers ============================
__device__ __forceinline__ uint32_t smem_u32(const void* p) {
    uint32_t a;
    asm("{ .reg .u64 t; cvta.to.shared.u64 t, %1; cvt.u32.u64 %0, t; }" : "=r"(a) : "l"(p));
    return a;
}
__device__ __forceinline__ void ldsm4(uint32_t r[4], uint32_t addr) {
    asm volatile("ldmatrix.sync.aligned.m8n8.x4.shared.b16 {%0,%1,%2,%3}, [%4];"
        : "=r"(r[0]), "=r"(r[1]), "=r"(r[2]), "=r"(r[3]) : "r"(addr));
}
__device__ __forceinline__ void ldsm4t(uint32_t r[4], uint32_t addr) {
    asm volatile("ldmatrix.sync.aligned.m8n8.x4.trans.shared.b16 {%0,%1,%2,%3}, [%4];"
        : "=r"(r[0]), "=r"(r[1]), "=r"(r[2]), "=r"(r[3]) : "r"(addr));
}
__device__ __forceinline__ void mma_f16(float c[4], const uint32_t a[4], uint32_t b0, uint32_t b1) {
    asm volatile(
        "mma.sync.aligned.m16n8k16.row.col.f32.f16.f16.f32 "
        "{%0,%1,%2,%3}, {%4,%5,%6,%7}, {%8,%9}, {%0,%1,%2,%3};\n"
        : "+f"(c[0]), "+f"(c[1]), "+f"(c[2]), "+f"(c[3])
        : "r"(a[0]), "r"(a[1]), "r"(a[2]), "r"(a[3]), "r"(b0), "r"(b1));
}
__device__ __forceinline__ uint32_t pack_h2(__half a, __half b) {
    __half2 h = __halves2half2(a, b);
    return *(uint32_t*)&h;
}
__device__ __forceinline__ float silu_f(float g) { return g / (1.f + __expf(-g)); }

// ============================ router ============================
__global__ void router_kernel(const float* __restrict__ x,
                              const float* __restrict__ rw,
                              const float* __restrict__ seg)
{
    int t = blockIdx.x;
    int tid = threadIdx.x;              // 64 threads
    __shared__ float xs[HH];
    __shared__ float lg[EE];
    __shared__ float red[64];
    const float* xr = x + (size_t)t*HH;
    for (int i = tid; i < HH; i += 64) xs[i] = xr[i];
    __syncthreads();
    if (tid < EE) {
        float a=0.f,b=0.f,c=0.f,d=0.f;
        for (int k = 0; k < HH; k += 4) {
            a = fmaf(xs[k+0], rw[(size_t)(k+0)*EE + tid], a);
            b = fmaf(xs[k+1], rw[(size_t)(k+1)*EE + tid], b);
            c = fmaf(xs[k+2], rw[(size_t)(k+2)*EE + tid], c);
            d = fmaf(xs[k+3], rw[(size_t)(k+3)*EE + tid], d);
        }
        lg[tid] = (a+b)+(c+d);
    }
    float p = 0.f;
    for (int k = tid; k < HH; k += 64) p = fmaf(xs[k], seg[k], p);
    red[tid] = p;
    __syncthreads();
    if (tid == 0) {
        float m = lg[0];
        for (int e = 1; e < EE; e++) m = fmaxf(m, lg[e]);
        float s = 0.f;
        for (int e = 0; e < EE; e++) { float v = __expf(lg[e]-m); lg[e] = v; s += v; }
        float inv = 1.f/s;
        for (int e = 0; e < EE; e++) lg[e] *= inv;
        for (int j = 0; j < TK; j++) {
            int bi = 0; float bv = lg[0];
            for (int e = 1; e < EE; e++) { if (lg[e] > bv) { bv = lg[e]; bi = e; } }
            g_topidx[t*TK+j] = bi;
            g_topw[t*TK+j]  = bv;
            lg[bi] = -1.f;
        }
        float ss = 0.f;
        for (int i = 0; i < 64; i++) ss += red[i];
        g_sig[t] = 1.f/(1.f + __expf(-ss));
    }
}

__global__ void build1_kernel()
{
    __shared__ int cnt[EE];
    int tid = threadIdx.x;              // 256
    if (tid < EE) cnt[tid] = 0;
    __syncthreads();
    for (int p = tid; p < NP; p += 256) atomicAdd(&cnt[g_topidx[p]], 1);
    __syncthreads();
    if (tid == 0) {
        int s = 0;
        for (int e = 0; e < EE; e++) { g_off[e] = s; s += cnt[e]; }
        g_off[EE] = s;
    }
}

__global__ void build2_kernel()
{
    __shared__ int sidx[NP];            // 32 KB
    int tid = threadIdx.x;              // 256, grid 32
    for (int i = tid; i < NP; i += 256) sidx[i] = g_topidx[i];
    __syncthreads();
    int p = blockIdx.x*256 + tid;
    int e = sidx[p];
    int r = 0;
    for (int q = 0; q < p; q++) r += (sidx[q] == e);
    int pos = g_off[e] + r;
    g_tok[pos] = p >> 2;
    g_pos[p]   = pos;
}

// ============================ HMMA GEMM ============================
// CTA tile 128x128, BK=32, fp16x2 split on A (hi/lo), B single fp16.
// smem stage: Ahi [128][40]h (10240B) | Alo (10240B) | B [32][136]h (8704B)
#define AHI 0
#define ALO 10240
#define BOF 20480
#define STG 29184
#define SMEM_BYTES (2*STG)

// stage: load one 32-k slab from gmem, convert to fp16(+lo), store to smem buffer.
// Registers are short-lived (consumed immediately) so 2 CTAs/SM fit in the RF.
template<int MODE, bool MOE>
__device__ __forceinline__ void fill_slab(char* base,
                                          const float* __restrict__ aptr,
                                          const float* __restrict__ bptr,
                                          int s, int N_, int ar, int ah, int bk, int bn)
{
    const float* ap = aptr + s*32;
    const float* bp = bptr + (size_t)s*32*N_;
    uint32_t wh[8], wl[8], wb[8];
    #pragma unroll
    for (int i = 0; i < 4; i++) {
        float4 a = *(const float4*)(ap + i*4);
        __half h0 = __float2half_rn(a.x), h1 = __float2half_rn(a.y);
        __half h2 = __float2half_rn(a.z), h3 = __float2half_rn(a.w);
        wh[2*i]   = pack_h2(h0, h1);
        wh[2*i+1] = pack_h2(h2, h3);
        wl[2*i]   = pack_h2(__float2half_rn(a.x - __half2float(h0)),
                            __float2half_rn(a.y - __half2float(h1)));
        wl[2*i+1] = pack_h2(__float2half_rn(a.z - __half2float(h2)),
                            __float2half_rn(a.w - __half2float(h3)));
    }
    #pragma unroll
    for (int i = 0; i < 4; i++) {
        float4 b = *(const float4*)(bp + i*4);
        wb[2*i]   = pack_h2(__float2half_rn(b.x), __float2half_rn(b.y));
        wb[2*i+1] = pack_h2(__float2half_rn(b.z), __float2half_rn(b.w));
    }
    char* pa = base + AHI + ar*80 + ah*2;
    *(uint4*)(pa)      = make_uint4(wh[0], wh[1], wh[2], wh[3]);
    *(uint4*)(pa + 16) = make_uint4(wh[4], wh[5], wh[6], wh[7]);
    char* pl = base + ALO + ar*80 + ah*2;
    *(uint4*)(pl)      = make_uint4(wl[0], wl[1], wl[2], wl[3]);
    *(uint4*)(pl + 16) = make_uint4(wl[4], wl[5], wl[6], wl[7]);
    char* pb = base + BOF + bk*272 + bn*2;
    *(uint4*)(pb)      = make_uint4(wb[0], wb[1], wb[2], wb[3]);
    *(uint4*)(pb + 16) = make_uint4(wb[4], wb[5], wb[6], wb[7]);
}

// MOE=false: MODE0 ybuf=x@shg | MODE1 ybuf=silu(ybuf)*(x@shu) | MODE2 out=sig*(ybuf@shd)
// MOE=true : MODE0 hbuf=x[tok]@wg[e] | MODE1 hbuf=silu(hbuf)*(x[tok]@wu[e]) | MODE2 pbuf=hbuf@wd[e]
template<int MODE, bool MOE>
__global__ void __launch_bounds__(256,2) gemm_hmma(const float* __restrict__ Aex,
                                                   const float* __restrict__ Bw,
                                                   float* __restrict__ Cex)
{
    constexpr int K = MOE ? ((MODE==2) ? FF : HH) : ((MODE==2) ? SS : HH);
    constexpr int N = MOE ? ((MODE==2) ? HH : FF) : ((MODE==2) ? HH : SS);
    constexpr int NSLAB = K/32;

    extern __shared__ __align__(16) char dsm[];
    const uint32_t sb = smem_u32(dsm);

    const int tid = threadIdx.x, lane = tid & 31, w = tid >> 5;
    const int wm = (w & 3)*32, wn = (w >> 2)*64;

    int e = 0, off = 0, cnt = TT;
    if (MOE) { e = blockIdx.z; off = g_off[e]; cnt = g_off[e+1] - off; }
    const int mb = blockIdx.y*128;
    if (MOE && mb >= cnt) return;
    const int nb = blockIdx.x*128;
    const float* Bp = MOE ? Bw + (size_t)e*K*N : Bw;
    const float* Abase = (!MOE && MODE==2) ? (const float*)g_ybuf
                       : ( MOE && MODE==2) ? (const float*)g_hbuf
                       : Aex;

    // fill mappings
    const int ar = tid >> 1, ah = (tid & 1)*16;
    const float* aptr;
    {
        int rl = mb + ar;
        if (MOE) {
            int rc = (rl < cnt) ? rl : (cnt - 1);
            if (MODE < 2) aptr = Abase + (size_t)g_tok[off + rc]*HH + ah;
            else          aptr = Abase + (size_t)(off + rc)*FF + ah;
        } else {
            aptr = Abase + (size_t)rl*K + ah;
        }
    }
    const int bk = tid >> 3, bn = (tid & 7)*16;
    const float* bptr = Bp + (size_t)bk*N + nb + bn;

    // fragment lane addresses (byte offsets within a stage)
    const int lr = lane & 15, lc = lane >> 4;
    const uint32_t aoff0 = (uint32_t)(((wm + lr)*40 + lc*8)*2);
    const uint32_t aoff1 = aoff0 + 16*80;
    uint32_t boff[4];
    #pragma unroll
    for (int np = 0; np < 4; np++)
        boff[np] = (uint32_t)((lr*136 + wn + np*16 + lc*8)*2) + BOF;

    float acc[2][8][4] = {};

    // prologue: slab 0
    fill_slab<MODE,MOE>(dsm, aptr, bptr, 0, N, ar, ah, bk, bn);
    __syncthreads();

    for (int s = 0; s < NSLAB; s++) {
        const uint32_t sbb = sb + (uint32_t)((s & 1)*STG);
        // fill NEXT slab into the other buffer (short-lived regs; other CTA's
        // warps cover the gmem latency while this CTA stalls on the STS)
        if (s + 1 < NSLAB)
            fill_slab<MODE,MOE>(dsm + ((s+1) & 1)*STG, aptr, bptr, s+1, N, ar, ah, bk, bn);

        #pragma unroll
        for (int ks = 0; ks < 2; ks++) {
            const uint32_t kbA = ks*32;        // 16 fp16 -> 32 bytes
            const uint32_t kbB = ks*16*272;    // 16 k-rows
            uint32_t a0h[4], a1h[4], a0l[4], a1l[4];
            ldsm4(a0h, sbb + AHI + aoff0 + kbA);
            ldsm4(a1h, sbb + AHI + aoff1 + kbA);
            ldsm4(a0l, sbb + ALO + aoff0 + kbA);
            ldsm4(a1l, sbb + ALO + aoff1 + kbA);
            #pragma unroll
            for (int np = 0; np < 4; np++) {
                uint32_t bb[4];
                ldsm4t(bb, sbb + boff[np] + kbB);
                mma_f16(acc[0][np*2],   a0h, bb[0], bb[1]);
                mma_f16(acc[0][np*2],   a0l, bb[0], bb[1]);
                mma_f16(acc[0][np*2+1], a0h, bb[2], bb[3]);
                mma_f16(acc[0][np*2+1], a0l, bb[2], bb[3]);
                mma_f16(acc[1][np*2],   a1h, bb[0], bb[1]);
                mma_f16(acc[1][np*2],   a1l, bb[0], bb[1]);
                mma_f16(acc[1][np*2+1], a1h, bb[2], bb[3]);
                mma_f16(acc[1][np*2+1], a1l, bb[2], bb[3]);
            }
        }
        __syncthreads();
    }

    // ---- epilogue ----
    #pragma unroll
    for (int mt = 0; mt < 2; mt++) {
        const int r0 = mb + wm + mt*16 + (lane >> 2);
        const int r1 = r0 + 8;
        const bool v0 = MOE ? (r0 < cnt) : true;
        const bool v1 = MOE ? (r1 < cnt) : true;
        #pragma unroll
        for (int nt = 0; nt < 8; nt++) {
            const int col = nb + wn + nt*8 + (lane & 3)*2;
            const float* c = acc[mt][nt];
            if (!MOE) {
                if (MODE == 0) {
                    *(float2*)&g_ybuf[(size_t)r0*SS + col] = make_float2(c[0], c[1]);
                    *(float2*)&g_ybuf[(size_t)r1*SS + col] = make_float2(c[2], c[3]);
                } else if (MODE == 1) {
                    float2 g0 = *(float2*)&g_ybuf[(size_t)r0*SS + col];
                    float2 g1 = *(float2*)&g_ybuf[(size_t)r1*SS + col];
                    *(float2*)&g_ybuf[(size_t)r0*SS + col] =
                        make_float2(silu_f(g0.x)*c[0], silu_f(g0.y)*c[1]);
                    *(float2*)&g_ybuf[(size_t)r1*SS + col] =
                        make_float2(silu_f(g1.x)*c[2], silu_f(g1.y)*c[3]);
                } else {
                    float s0 = g_sig[r0], s1 = g_sig[r1];
                    *(float2*)&Cex[(size_t)r0*HH + col] = make_float2(s0*c[0], s0*c[1]);
                    *(float2*)&Cex[(size_t)r1*HH + col] = make_float2(s1*c[2], s1*c[3]);
                }
            } else {
                if (MODE == 0) {
                    if (v0) *(float2*)&g_hbuf[(size_t)(off+r0)*FF + col] = make_float2(c[0], c[1]);
                    if (v1) *(float2*)&g_hbuf[(size_t)(off+r1)*FF + col] = make_float2(c[2], c[3]);
                } else if (MODE == 1) {
                    if (v0) {
                        float2 g = *(float2*)&g_hbuf[(size_t)(off+r0)*FF + col];
                        *(float2*)&g_hbuf[(size_t)(off+r0)*FF + col] =
                            make_float2(silu_f(g.x)*c[0], silu_f(g.y)*c[1]);
                    }
                    if (v1) {
                        float2 g = *(float2*)&g_hbuf[(size_t)(off+r1)*FF + col];
                        *(float2*)&g_hbuf[(size_t)(off+r1)*FF + col] =
                            make_float2(silu_f(g.x)*c[2], silu_f(g.y)*c[3]);
                    }
                } else {
                    if (v0) *(float2*)&g_pbuf[(size_t)(off+r0)*HH + col] = make_float2(c[0], c[1]);
                    if (v1) *(float2*)&g_pbuf[(size_t)(off+r1)*HH + col] = make_float2(c[2], c[3]);
                }
            }
        }
    }
}

// ============================ combine ============================
__global__ void combine_kernel(float* __restrict__ out)
{
    int t = blockIdx.x, tid = threadIdx.x;
    int p0 = g_pos[t*4+0], p1 = g_pos[t*4+1], p2 = g_pos[t*4+2], p3 = g_pos[t*4+3];
    float w0 = g_topw[t*4+0], w1 = g_topw[t*4+1], w2 = g_topw[t*4+2], w3 = g_topw[t*4+3];
    const float* r0 = g_pbuf + (size_t)p0*HH;
    const float* r1 = g_pbuf + (size_t)p1*HH;
    const float* r2 = g_pbuf + (size_t)p2*HH;
    const float* r3 = g_pbuf + (size_t)p3*HH;
    for (int c = tid; c < HH; c += 256) {
        float v = out[(size_t)t*HH + c];
        v = fmaf(w0, r0[c], v);
        v = fmaf(w1, r1[c], v);
        v = fmaf(w2, r2[c], v);
        v = fmaf(w3, r3[c], v);
        out[(size_t)t*HH + c] = v;
    }
}

// ============================ launch ============================
extern "C" void kernel_launch(void* const* d_in, const int* in_sizes, int n_in,
                              void* d_out, int out_size)
{
    const float* x   = (const float*)d_in[0];
    const float* rw  = (const float*)d_in[1];
    const float* wg  = (const float*)d_in[2];
    const float* wu  = (const float*)d_in[3];
    const float* wd  = (const float*)d_in[4];
    const float* shg = (const float*)d_in[5];
    const float* shu = (const float*)d_in[6];
    const float* shd = (const float*)d_in[7];
    const float* seg = (const float*)d_in[8];
    float* out = (float*)d_out;
    (void)in_sizes; (void)n_in; (void)out_size;

    cudaFuncSetAttribute(gemm_hmma<0,false>, cudaFuncAttributeMaxDynamicSharedMemorySize, SMEM_BYTES);
    cudaFuncSetAttribute(gemm_hmma<1,false>, cudaFuncAttributeMaxDynamicSharedMemorySize, SMEM_BYTES);
    cudaFuncSetAttribute(gemm_hmma<2,false>, cudaFuncAttributeMaxDynamicSharedMemorySize, SMEM_BYTES);
    cudaFuncSetAttribute(gemm_hmma<0,true>,  cudaFuncAttributeMaxDynamicSharedMemorySize, SMEM_BYTES);
    cudaFuncSetAttribute(gemm_hmma<1,true>,  cudaFuncAttributeMaxDynamicSharedMemorySize, SMEM_BYTES);
    cudaFuncSetAttribute(gemm_hmma<2,true>,  cudaFuncAttributeMaxDynamicSharedMemorySize, SMEM_BYTES);

    router_kernel<<<TT, 64>>>(x, rw, seg);
    build1_kernel<<<1, 256>>>();
    build2_kernel<<<32, 256>>>();

    // shared expert
    gemm_hmma<0,false><<<dim3(SS/128, TT/128), 256, SMEM_BYTES>>>(x, shg, nullptr);
    gemm_hmma<1,false><<<dim3(SS/128, TT/128), 256, SMEM_BYTES>>>(x, shu, nullptr);
    gemm_hmma<2,false><<<dim3(HH/128, TT/128), 256, SMEM_BYTES>>>(nullptr, shd, out);

    // MoE experts
    gemm_hmma<0,true><<<dim3(FF/128, TT/128, EE), 256, SMEM_BYTES>>>(x, wg, nullptr);
    gemm_hmma<1,true><<<dim3(FF/128, TT/128, EE), 256, SMEM_BYTES>>>(x, wu, nullptr);
    gemm_hmma<2,true><<<dim3(HH/128, TT/128, EE), 256, SMEM_BYTES>>>(nullptr, wd, nullptr);

    combine_kernel<<<TT, 256>>>(out);
}